// round 8
// baseline (speedup 1.0000x reference)
#include <cuda_runtime.h>
#include <cuda_bf16.h>
#include <cstdint>

#define N_PATHS 2048
#define N_STEPS 512
#define N_FWD   40
#define DT      (1.0f / 512.0f)
#define SHIFT   0.02f
#define LOG2E   1.4426950408889634f
#define N_CHUNK 16
#define CHUNK_T (N_STEPS / N_CHUNK)   // 32
#define PATH_THREADS (N_CHUNK * N_FWD)  // 640

#define KC      32                    // conv k-chunk
#define SA      36                    // padded row stride (floats)

// ---------------- device scratch ----------------
__device__ float  g_cw2[N_STEPS];               // inclusive prefix sum of w^2
__device__ float4 g_fbm4[N_PATHS * N_STEPS];    // fbm4[p][t][0..3]

// Toeplitz weight, cancellation-free in fp32:
// w[j] = ((j+1)^0.6 - j^0.6)/0.6 * 2^3.6 / Gamma(0.6)
__device__ __forceinline__ float toeplitz_w(int j) {
    const float scale = 12.125732f / 1.4891922f;
    float num;
    if (j == 0) {
        num = 1.0f / 0.6f;
    } else {
        float fj = (float)j;
        float p6 = exp2f(0.6f * log2f(fj));
        float em = expm1f(0.6f * log1pf(1.0f / fj));
        num = p6 * em * (1.0f / 0.6f);
    }
    return num * scale;
}

__device__ __forceinline__ uint32_t f2tf32(float f) {
    uint32_t u;
    asm("cvt.rna.tf32.f32 %0, %1;" : "=r"(u) : "f"(f));
    return u;
}

__device__ __forceinline__ void mma_tf32(float* c, const uint32_t* a, const uint32_t* b) {
    asm volatile(
        "mma.sync.aligned.m16n8k8.row.col.f32.tf32.tf32.f32 "
        "{%0,%1,%2,%3}, {%4,%5,%6,%7}, {%8,%9}, {%0,%1,%2,%3};"
        : "+f"(c[0]), "+f"(c[1]), "+f"(c[2]), "+f"(c[3])
        : "r"(a[0]), "r"(a[1]), "r"(a[2]), "r"(a[3]), "r"(b[0]), "r"(b[1]));
}

// ---------------- kernel 1: conv as triangular Toeplitz GEMM (tf32 HMMA) ----
__global__ __launch_bounds__(256) void k_conv_mma(const float* __restrict__ dz) {
    __shared__ uint32_t sA[128 * SA];
    __shared__ uint32_t sB[128 * SA];
    __shared__ float    swf[N_STEPS];
    __shared__ float    sscan[256];

    const int tid  = threadIdx.x;
    const int wid  = tid >> 5;
    const int lane = tid & 31;
    const int bid  = blockIdx.x;
    const int ti   = 3 - (bid >> 6);     // heavy tiles first
    const int cg   = bid & 63;
    const int p0   = cg * 32;
    const int t0   = 128 * ti;
    const int mw   = (wid >> 2) * 64;
    const int nw   = (wid & 3) * 32;

    for (int i = tid; i < N_STEPS; i += 256) swf[i] = toeplitz_w(i);
    __syncthreads();

    if (bid == 0) {
        float wa = swf[2 * tid], wb = swf[2 * tid + 1];
        float w2b = wb * wb;
        sscan[tid] = wa * wa + w2b;
        __syncthreads();
        #pragma unroll
        for (int off = 1; off < 256; off <<= 1) {
            float v = sscan[tid];
            float u = (tid >= off) ? sscan[tid - off] : 0.f;
            __syncthreads();
            sscan[tid] = v + u;
            __syncthreads();
        }
        float inc = sscan[tid];
        g_cw2[2 * tid + 1] = inc;
        g_cw2[2 * tid]     = inc - w2b;
        __syncthreads();
    }

    float c[4][4][4];
    #pragma unroll
    for (int mt = 0; mt < 4; ++mt)
        #pragma unroll
        for (int nt = 0; nt < 4; ++nt)
            #pragma unroll
            for (int e = 0; e < 4; ++e) c[mt][nt][e] = 0.f;

    const float4* dzv = (const float4*)dz;
    const int n_kc = 4 * ti + 4;

    for (int kc = 0; kc < n_kc; ++kc) {
        const int s0   = KC * kc;
        const int toff = t0 - s0;
        __syncthreads();

        #pragma unroll
        for (int r = 0; r < 16; ++r) {
            int u = tid + 256 * r;
            int i = u >> 5, j = u & 31;
            int q = toff + i - j;
            float v = (q >= 0) ? swf[q] : 0.f;
            sA[i * SA + j] = f2tf32(v);
        }
        #pragma unroll
        for (int r = 0; r < 4; ++r) {
            int u  = tid + 256 * r;
            int pl = u >> 5, k = u & 31;
            float4 x = dzv[(size_t)(p0 + pl) * N_STEPS + s0 + k];
            int n = 4 * pl;
            sB[(n + 0) * SA + k] = f2tf32(x.x);
            sB[(n + 1) * SA + k] = f2tf32(x.y);
            sB[(n + 2) * SA + k] = f2tf32(x.z);
            sB[(n + 3) * SA + k] = f2tf32(x.w);
        }
        __syncthreads();

        #pragma unroll
        for (int ks = 0; ks < 4; ++ks) {
            int kb = 8 * ks;
            uint32_t bf[4][2];
            #pragma unroll
            for (int nt = 0; nt < 4; ++nt) {
                int col = nw + 8 * nt + (lane >> 2);
                bf[nt][0] = sB[col * SA + kb + (lane & 3)];
                bf[nt][1] = sB[col * SA + kb + 4 + (lane & 3)];
            }
            #pragma unroll
            for (int mt = 0; mt < 4; ++mt) {
                int row = mw + 16 * mt + (lane >> 2);
                uint32_t af[4];
                af[0] = sA[row * SA + kb + (lane & 3)];
                af[1] = sA[(row + 8) * SA + kb + (lane & 3)];
                af[2] = sA[row * SA + kb + 4 + (lane & 3)];
                af[3] = sA[(row + 8) * SA + kb + 4 + (lane & 3)];
                #pragma unroll
                for (int nt = 0; nt < 4; ++nt)
                    mma_tf32(c[mt][nt], af, bf[nt]);
            }
        }
    }

    float2* dst = (float2*)g_fbm4;
    #pragma unroll
    for (int mt = 0; mt < 4; ++mt) {
        #pragma unroll
        for (int nt = 0; nt < 4; ++nt) {
            int row  = mw + 16 * mt + (lane >> 2);
            int col  = nw + 8 * nt + 2 * (lane & 3);
            int path = p0 + (col >> 2);
            int dp   = (col & 3) >> 1;
            size_t base = ((size_t)path * N_STEPS + t0 + row) * 2 + dp;
            dst[base]      = make_float2(c[mt][nt][0], c[mt][nt][1]);
            dst[base + 16] = make_float2(c[mt][nt][2], c[mt][nt][3]);
        }
    }
}

// ---------------- kernel 2: per-path chunked scan, dF carried in registers --
// One block = one path, 640 threads = 16 chunks x 40 forwards.
// Phase 1: compute 32 dF values into REGISTERS (+ chunk partial sum).
// Phase 2: chunk offset from spart.
// Phase 3: scan from registers + streaming stores (no recompute, no re-read).
__global__ __launch_bounds__(PATH_THREADS, 1) void k_path(
    const float* __restrict__ dz,
    const float* __restrict__ F0,
    const float* __restrict__ alphas,
    const float* __restrict__ rhos,
    const float* __restrict__ nus,
    const float* __restrict__ tau,
    const float* __restrict__ L,
    const float* __restrict__ Lam,
    float* __restrict__ out)
{
    __shared__ float4 sfb[N_STEPS];                // 8 KB
    __shared__ float4 sdzs[N_STEPS];               // 8 KB
    __shared__ float  scw[N_STEPS];                // 2 KB
    __shared__ float  spart[N_CHUNK * N_FWD];      // 2.5 KB
    __shared__ float  som[N_FWD];

    int u = threadIdx.x;            // 0..639
    int c = u / N_FWD;              // chunk 0..15
    int n = u - c * N_FWD;          // forward 0..39
    int p = blockIdx.x;

    const float4* fb  = &g_fbm4[(size_t)p * N_STEPS];
    const float4* dzp = (const float4*)dz + (size_t)p * N_STEPS;
    if (u < N_STEPS) {
        sfb[u]  = fb[u];
        sdzs[u] = dzp[u];
        scw[u]  = g_cw2[u];
    }
    if (u < N_FWD) {
        float f0m = F0[u];
        float vsm = alphas[u] * sqrtf(fabsf(f0m + SHIFT));
        som[u] = tau[u] * vsm / (1.f + tau[u] * f0m);
    }

    float f0n = F0[n];
    float vs  = alphas[n] * sqrtf(fabsf(f0n + SHIFT));
    float rho = rhos[n];
    float nu  = nus[n];
    float sq  = sqrtf(fmaxf(1.f - rho * rho, 0.f));
    float l0 = L[n * 3 + 0], l1 = L[n * 3 + 1], l2 = L[n * 3 + 2];
    float a0 = nu * rho * l0 * LOG2E;
    float a1 = nu * rho * l1 * LOG2E;
    float a2 = nu * rho * l2 * LOG2E;
    float a3 = nu * sq * LOG2E;
    float bb = 0.5f * nu * nu * DT * LOG2E;
    float w0 = vs * l0, w1 = vs * l1, w2 = vs * l2;

    __syncthreads();

    float mdot = 0.f;
    #pragma unroll 8
    for (int m = 0; m < N_FWD; ++m)
        mdot = fmaf(Lam[n * N_FWD + m], som[m], mdot);
    float mu0dt = -vs * mdot * DT;

    // ---- phase 1: dF into registers + partial sum ----
    int t0 = c * CHUNK_T;
    float dF[CHUNK_T];
    float psum = 0.f;
    #pragma unroll
    for (int i = 0; i < CHUNK_T; ++i) {
        int t = t0 + i;
        float4 f = sfb[t];
        float4 d = sdzs[t];
        float arg = fmaf(a0, f.x,
                    fmaf(a1, f.y,
                    fmaf(a2, f.z,
                    fmaf(a3, f.w, -bb * scw[t]))));
        float uv;
        asm("ex2.approx.f32 %0, %1;" : "=f"(uv) : "f"(arg));
        float wr = fmaf(w0, d.x, fmaf(w1, d.y, w2 * d.z));
        float v = uv * fmaf(mu0dt, uv, wr);
        dF[i] = v;
        psum += v;
    }
    spart[c * N_FWD + n] = psum;
    __syncthreads();

    // ---- phase 2: chunk offset ----
    float acc = f0n;
    #pragma unroll
    for (int cc = 0; cc < N_CHUNK - 1; ++cc)
        if (cc < c) acc += spart[cc * N_FWD + n];

    // ---- phase 3: scan from registers + stores ----
    float* op = out + (size_t)p * 513 * N_FWD + n;
    if (c == 0) __stcs(op, f0n);
    op += (size_t)(t0 + 1) * N_FWD;
    #pragma unroll
    for (int i = 0; i < CHUNK_T; ++i) {
        acc += dF[i];
        __stcs(op, acc);
        op += N_FWD;
    }
}

extern "C" void kernel_launch(void* const* d_in, const int* in_sizes, int n_in,
                              void* d_out, int out_size) {
    const float* dz     = (const float*)d_in[0];
    const float* F0     = (const float*)d_in[1];
    const float* alphas = (const float*)d_in[2];
    const float* rhos   = (const float*)d_in[3];
    const float* nus    = (const float*)d_in[4];
    const float* tau    = (const float*)d_in[5];
    const float* L      = (const float*)d_in[6];
    const float* Lam    = (const float*)d_in[7];
    float* out = (float*)d_out;

    k_conv_mma<<<256, 256>>>(dz);
    k_path<<<N_PATHS, PATH_THREADS>>>(dz, F0, alphas, rhos, nus, tau, L, Lam, out);
}

// round 9
// speedup vs baseline: 1.2703x; 1.2703x over previous
#include <cuda_runtime.h>
#include <cuda_bf16.h>
#include <cstdint>

#define N_PATHS 2048
#define N_STEPS 512
#define N_FWD   40
#define DT      (1.0f / 512.0f)
#define SHIFT   0.02f
#define LOG2E   1.4426950408889634f
#define N_CHUNK 8
#define CHUNK_T (N_STEPS / N_CHUNK)   // 64

#define KC      32                    // conv k-chunk
#define SA      36                    // padded row stride (floats)

// ---------------- device scratch ----------------
__device__ float  g_cw2[N_STEPS];               // inclusive prefix sum of w^2
__device__ float4 g_fbm4[N_PATHS * N_STEPS];    // fbm4[p][t][0..3]

// Toeplitz weight, cancellation-free in fp32:
// w[j] = ((j+1)^0.6 - j^0.6)/0.6 * 2^3.6 / Gamma(0.6)
__device__ __forceinline__ float toeplitz_w(int j) {
    const float scale = 12.125732f / 1.4891922f;
    float num;
    if (j == 0) {
        num = 1.0f / 0.6f;
    } else {
        float fj = (float)j;
        float p6 = exp2f(0.6f * log2f(fj));
        float em = expm1f(0.6f * log1pf(1.0f / fj));
        num = p6 * em * (1.0f / 0.6f);
    }
    return num * scale;
}

__device__ __forceinline__ uint32_t f2tf32(float f) {
    uint32_t u;
    asm("cvt.rna.tf32.f32 %0, %1;" : "=r"(u) : "f"(f));
    return u;
}

__device__ __forceinline__ void mma_tf32(float* c, const uint32_t* a, const uint32_t* b) {
    asm volatile(
        "mma.sync.aligned.m16n8k8.row.col.f32.tf32.tf32.f32 "
        "{%0,%1,%2,%3}, {%4,%5,%6,%7}, {%8,%9}, {%0,%1,%2,%3};"
        : "+f"(c[0]), "+f"(c[1]), "+f"(c[2]), "+f"(c[3])
        : "r"(a[0]), "r"(a[1]), "r"(a[2]), "r"(a[3]), "r"(b[0]), "r"(b[1]));
}

// ---------------- kernel 1: conv as triangular Toeplitz GEMM (tf32 HMMA) ----
// (unchanged from R7: 32us, tensor-pipe resident)
__global__ __launch_bounds__(256) void k_conv_mma(const float* __restrict__ dz) {
    __shared__ uint32_t sA[128 * SA];
    __shared__ uint32_t sB[128 * SA];
    __shared__ float    swf[N_STEPS];
    __shared__ float    sscan[256];

    const int tid  = threadIdx.x;
    const int wid  = tid >> 5;
    const int lane = tid & 31;
    const int bid  = blockIdx.x;
    const int ti   = 3 - (bid >> 6);     // heavy tiles first
    const int cg   = bid & 63;
    const int p0   = cg * 32;
    const int t0   = 128 * ti;
    const int mw   = (wid >> 2) * 64;
    const int nw   = (wid & 3) * 32;

    for (int i = tid; i < N_STEPS; i += 256) swf[i] = toeplitz_w(i);
    __syncthreads();

    if (bid == 0) {
        float wa = swf[2 * tid], wb = swf[2 * tid + 1];
        float w2b = wb * wb;
        sscan[tid] = wa * wa + w2b;
        __syncthreads();
        #pragma unroll
        for (int off = 1; off < 256; off <<= 1) {
            float v = sscan[tid];
            float u = (tid >= off) ? sscan[tid - off] : 0.f;
            __syncthreads();
            sscan[tid] = v + u;
            __syncthreads();
        }
        float inc = sscan[tid];
        g_cw2[2 * tid + 1] = inc;
        g_cw2[2 * tid]     = inc - w2b;
        __syncthreads();
    }

    float c[4][4][4];
    #pragma unroll
    for (int mt = 0; mt < 4; ++mt)
        #pragma unroll
        for (int nt = 0; nt < 4; ++nt)
            #pragma unroll
            for (int e = 0; e < 4; ++e) c[mt][nt][e] = 0.f;

    const float4* dzv = (const float4*)dz;
    const int n_kc = 4 * ti + 4;

    for (int kc = 0; kc < n_kc; ++kc) {
        const int s0   = KC * kc;
        const int toff = t0 - s0;
        __syncthreads();

        #pragma unroll
        for (int r = 0; r < 16; ++r) {
            int u = tid + 256 * r;
            int i = u >> 5, j = u & 31;
            int q = toff + i - j;
            float v = (q >= 0) ? swf[q] : 0.f;
            sA[i * SA + j] = f2tf32(v);
        }
        #pragma unroll
        for (int r = 0; r < 4; ++r) {
            int u  = tid + 256 * r;
            int pl = u >> 5, k = u & 31;
            float4 x = dzv[(size_t)(p0 + pl) * N_STEPS + s0 + k];
            int n = 4 * pl;
            sB[(n + 0) * SA + k] = f2tf32(x.x);
            sB[(n + 1) * SA + k] = f2tf32(x.y);
            sB[(n + 2) * SA + k] = f2tf32(x.z);
            sB[(n + 3) * SA + k] = f2tf32(x.w);
        }
        __syncthreads();

        #pragma unroll
        for (int ks = 0; ks < 4; ++ks) {
            int kb = 8 * ks;
            uint32_t bf[4][2];
            #pragma unroll
            for (int nt = 0; nt < 4; ++nt) {
                int col = nw + 8 * nt + (lane >> 2);
                bf[nt][0] = sB[col * SA + kb + (lane & 3)];
                bf[nt][1] = sB[col * SA + kb + 4 + (lane & 3)];
            }
            #pragma unroll
            for (int mt = 0; mt < 4; ++mt) {
                int row = mw + 16 * mt + (lane >> 2);
                uint32_t af[4];
                af[0] = sA[row * SA + kb + (lane & 3)];
                af[1] = sA[(row + 8) * SA + kb + (lane & 3)];
                af[2] = sA[row * SA + kb + 4 + (lane & 3)];
                af[3] = sA[(row + 8) * SA + kb + 4 + (lane & 3)];
                #pragma unroll
                for (int nt = 0; nt < 4; ++nt)
                    mma_tf32(c[mt][nt], af, bf[nt]);
            }
        }
    }

    float2* dst = (float2*)g_fbm4;
    #pragma unroll
    for (int mt = 0; mt < 4; ++mt) {
        #pragma unroll
        for (int nt = 0; nt < 4; ++nt) {
            int row  = mw + 16 * mt + (lane >> 2);
            int col  = nw + 8 * nt + 2 * (lane & 3);
            int path = p0 + (col >> 2);
            int dp   = (col & 3) >> 1;
            size_t base = ((size_t)path * N_STEPS + t0 + row) * 2 + dp;
            dst[base]      = make_float2(c[mt][nt][0], c[mt][nt][1]);
            dst[base + 16] = make_float2(c[mt][nt][2], c[mt][nt][3]);
        }
    }
}

// ---------------- kernel 2: per-path chunked scan (R5 shape, packed reads) --
// 320 threads = 8 chunks x 40 forwards. cw packed into sdzs[t].w (d.w unused)
// -> 2 LDS.128 per t instead of 2xLDS.128 + LDS.32.
__global__ __launch_bounds__(320) void k_path(
    const float* __restrict__ dz,
    const float* __restrict__ F0,
    const float* __restrict__ alphas,
    const float* __restrict__ rhos,
    const float* __restrict__ nus,
    const float* __restrict__ tau,
    const float* __restrict__ L,
    const float* __restrict__ Lam,
    float* __restrict__ out)
{
    __shared__ float4 sfb[N_STEPS];                // 8 KB
    __shared__ float4 sdzs[N_STEPS];               // 8 KB (w slot = cw2[t])
    __shared__ float  spart[N_CHUNK * N_FWD];      // 1.25 KB
    __shared__ float  som[N_FWD];

    int u = threadIdx.x;
    int c = u / N_FWD;
    int n = u - c * N_FWD;
    int p = blockIdx.x;

    const float4* fb  = &g_fbm4[(size_t)p * N_STEPS];
    const float4* dzp = (const float4*)dz + (size_t)p * N_STEPS;
    {
        float4 d = dzp[u];
        d.w = g_cw2[u];                 // pack cw into unused lane
        sfb[u]  = fb[u];
        sdzs[u] = d;
    }
    if (u + 320 < N_STEPS) {
        float4 d = dzp[u + 320];
        d.w = g_cw2[u + 320];
        sfb[u + 320]  = fb[u + 320];
        sdzs[u + 320] = d;
    }
    if (u < N_FWD) {
        float f0m = F0[u];
        float vsm = alphas[u] * sqrtf(fabsf(f0m + SHIFT));
        som[u] = tau[u] * vsm / (1.f + tau[u] * f0m);
    }

    float f0n = F0[n];
    float vs  = alphas[n] * sqrtf(fabsf(f0n + SHIFT));
    float rho = rhos[n];
    float nu  = nus[n];
    float sq  = sqrtf(fmaxf(1.f - rho * rho, 0.f));
    float l0 = L[n * 3 + 0], l1 = L[n * 3 + 1], l2 = L[n * 3 + 2];
    float a0 = nu * rho * l0 * LOG2E;
    float a1 = nu * rho * l1 * LOG2E;
    float a2 = nu * rho * l2 * LOG2E;
    float a3 = nu * sq * LOG2E;
    float bb = 0.5f * nu * nu * DT * LOG2E;
    float w0 = vs * l0, w1 = vs * l1, w2 = vs * l2;

    __syncthreads();

    float mdot = 0.f;
    #pragma unroll 8
    for (int m = 0; m < N_FWD; ++m)
        mdot = fmaf(Lam[n * N_FWD + m], som[m], mdot);
    float mu0dt = -vs * mdot * DT;

    // ---- phase 1: partial sum of my chunk's dF ----
    int t0 = c * CHUNK_T;
    float psum = 0.f;
    #pragma unroll 4
    for (int i = 0; i < CHUNK_T; ++i) {
        int t = t0 + i;
        float4 f = sfb[t];
        float4 d = sdzs[t];                 // d.w = cw2[t]
        float arg = fmaf(a0, f.x,
                    fmaf(a1, f.y,
                    fmaf(a2, f.z,
                    fmaf(a3, f.w, -bb * d.w))));
        float uv;
        asm("ex2.approx.f32 %0, %1;" : "=f"(uv) : "f"(arg));
        float wr = fmaf(w0, d.x, fmaf(w1, d.y, w2 * d.z));
        psum += uv * fmaf(mu0dt, uv, wr);
    }
    spart[c * N_FWD + n] = psum;
    __syncthreads();

    // ---- phase 2: chunk offset ----
    float acc = f0n;
    #pragma unroll
    for (int cc = 0; cc < N_CHUNK - 1; ++cc)
        if (cc < c) acc += spart[cc * N_FWD + n];

    // ---- phase 3: recompute dF (bit-identical), scan, store ----
    float* op = out + (size_t)p * 513 * N_FWD + n;
    if (c == 0) __stcs(op, f0n);
    op += (size_t)(t0 + 1) * N_FWD;
    #pragma unroll 4
    for (int i = 0; i < CHUNK_T; ++i) {
        int t = t0 + i;
        float4 f = sfb[t];
        float4 d = sdzs[t];
        float arg = fmaf(a0, f.x,
                    fmaf(a1, f.y,
                    fmaf(a2, f.z,
                    fmaf(a3, f.w, -bb * d.w))));
        float uv;
        asm("ex2.approx.f32 %0, %1;" : "=f"(uv) : "f"(arg));
        float wr = fmaf(w0, d.x, fmaf(w1, d.y, w2 * d.z));
        acc += uv * fmaf(mu0dt, uv, wr);
        __stcs(op, acc);
        op += N_FWD;
    }
}

extern "C" void kernel_launch(void* const* d_in, const int* in_sizes, int n_in,
                              void* d_out, int out_size) {
    const float* dz     = (const float*)d_in[0];
    const float* F0     = (const float*)d_in[1];
    const float* alphas = (const float*)d_in[2];
    const float* rhos   = (const float*)d_in[3];
    const float* nus    = (const float*)d_in[4];
    const float* tau    = (const float*)d_in[5];
    const float* L      = (const float*)d_in[6];
    const float* Lam    = (const float*)d_in[7];
    float* out = (float*)d_out;

    k_conv_mma<<<256, 256>>>(dz);
    k_path<<<N_PATHS, 320>>>(dz, F0, alphas, rhos, nus, tau, L, Lam, out);
}

// round 10
// speedup vs baseline: 1.5850x; 1.2477x over previous
#include <cuda_runtime.h>
#include <cuda_bf16.h>
#include <cstdint>

#define N_PATHS 2048
#define N_STEPS 512
#define N_FWD   40
#define DT      (1.0f / 512.0f)
#define SHIFT   0.02f
#define LOG2E   1.4426950408889634f

#define KC      32                    // conv k-chunk
#define SA      36                    // padded row stride (floats)

#define PPB     4                     // paths per block in k_path
#define PT      (PPB * N_FWD)         // 160 threads

// ---------------- device scratch ----------------
__device__ float  g_cw2[N_STEPS];               // inclusive prefix sum of w^2
__device__ float4 g_fbm4[N_PATHS * N_STEPS];    // fbm4[p][t][0..3]

// Toeplitz weight, cancellation-free in fp32:
// w[j] = ((j+1)^0.6 - j^0.6)/0.6 * 2^3.6 / Gamma(0.6)
__device__ __forceinline__ float toeplitz_w(int j) {
    const float scale = 12.125732f / 1.4891922f;
    float num;
    if (j == 0) {
        num = 1.0f / 0.6f;
    } else {
        float fj = (float)j;
        float p6 = exp2f(0.6f * log2f(fj));
        float em = expm1f(0.6f * log1pf(1.0f / fj));
        num = p6 * em * (1.0f / 0.6f);
    }
    return num * scale;
}

__device__ __forceinline__ uint32_t f2tf32(float f) {
    uint32_t u;
    asm("cvt.rna.tf32.f32 %0, %1;" : "=r"(u) : "f"(f));
    return u;
}

__device__ __forceinline__ void mma_tf32(float* c, const uint32_t* a, const uint32_t* b) {
    asm volatile(
        "mma.sync.aligned.m16n8k8.row.col.f32.tf32.tf32.f32 "
        "{%0,%1,%2,%3}, {%4,%5,%6,%7}, {%8,%9}, {%0,%1,%2,%3};"
        : "+f"(c[0]), "+f"(c[1]), "+f"(c[2]), "+f"(c[3])
        : "r"(a[0]), "r"(a[1]), "r"(a[2]), "r"(a[3]), "r"(b[0]), "r"(b[1]));
}

// ---------------- kernel 1: conv as triangular Toeplitz GEMM (tf32 HMMA) ----
// (unchanged from R7)
__global__ __launch_bounds__(256) void k_conv_mma(const float* __restrict__ dz) {
    __shared__ uint32_t sA[128 * SA];
    __shared__ uint32_t sB[128 * SA];
    __shared__ float    swf[N_STEPS];
    __shared__ float    sscan[256];

    const int tid  = threadIdx.x;
    const int wid  = tid >> 5;
    const int lane = tid & 31;
    const int bid  = blockIdx.x;
    const int ti   = 3 - (bid >> 6);     // heavy tiles first
    const int cg   = bid & 63;
    const int p0   = cg * 32;
    const int t0   = 128 * ti;
    const int mw   = (wid >> 2) * 64;
    const int nw   = (wid & 3) * 32;

    for (int i = tid; i < N_STEPS; i += 256) swf[i] = toeplitz_w(i);
    __syncthreads();

    if (bid == 0) {
        float wa = swf[2 * tid], wb = swf[2 * tid + 1];
        float w2b = wb * wb;
        sscan[tid] = wa * wa + w2b;
        __syncthreads();
        #pragma unroll
        for (int off = 1; off < 256; off <<= 1) {
            float v = sscan[tid];
            float u = (tid >= off) ? sscan[tid - off] : 0.f;
            __syncthreads();
            sscan[tid] = v + u;
            __syncthreads();
        }
        float inc = sscan[tid];
        g_cw2[2 * tid + 1] = inc;
        g_cw2[2 * tid]     = inc - w2b;
        __syncthreads();
    }

    float c[4][4][4];
    #pragma unroll
    for (int mt = 0; mt < 4; ++mt)
        #pragma unroll
        for (int nt = 0; nt < 4; ++nt)
            #pragma unroll
            for (int e = 0; e < 4; ++e) c[mt][nt][e] = 0.f;

    const float4* dzv = (const float4*)dz;
    const int n_kc = 4 * ti + 4;

    for (int kc = 0; kc < n_kc; ++kc) {
        const int s0   = KC * kc;
        const int toff = t0 - s0;
        __syncthreads();

        #pragma unroll
        for (int r = 0; r < 16; ++r) {
            int u = tid + 256 * r;
            int i = u >> 5, j = u & 31;
            int q = toff + i - j;
            float v = (q >= 0) ? swf[q] : 0.f;
            sA[i * SA + j] = f2tf32(v);
        }
        #pragma unroll
        for (int r = 0; r < 4; ++r) {
            int u  = tid + 256 * r;
            int pl = u >> 5, k = u & 31;
            float4 x = dzv[(size_t)(p0 + pl) * N_STEPS + s0 + k];
            int n = 4 * pl;
            sB[(n + 0) * SA + k] = f2tf32(x.x);
            sB[(n + 1) * SA + k] = f2tf32(x.y);
            sB[(n + 2) * SA + k] = f2tf32(x.z);
            sB[(n + 3) * SA + k] = f2tf32(x.w);
        }
        __syncthreads();

        #pragma unroll
        for (int ks = 0; ks < 4; ++ks) {
            int kb = 8 * ks;
            uint32_t bf[4][2];
            #pragma unroll
            for (int nt = 0; nt < 4; ++nt) {
                int col = nw + 8 * nt + (lane >> 2);
                bf[nt][0] = sB[col * SA + kb + (lane & 3)];
                bf[nt][1] = sB[col * SA + kb + 4 + (lane & 3)];
            }
            #pragma unroll
            for (int mt = 0; mt < 4; ++mt) {
                int row = mw + 16 * mt + (lane >> 2);
                uint32_t af[4];
                af[0] = sA[row * SA + kb + (lane & 3)];
                af[1] = sA[(row + 8) * SA + kb + (lane & 3)];
                af[2] = sA[row * SA + kb + 4 + (lane & 3)];
                af[3] = sA[(row + 8) * SA + kb + 4 + (lane & 3)];
                #pragma unroll
                for (int nt = 0; nt < 4; ++nt)
                    mma_tf32(c[mt][nt], af, bf[nt]);
            }
        }
    }

    float2* dst = (float2*)g_fbm4;
    #pragma unroll
    for (int mt = 0; mt < 4; ++mt) {
        #pragma unroll
        for (int nt = 0; nt < 4; ++nt) {
            int row  = mw + 16 * mt + (lane >> 2);
            int col  = nw + 8 * nt + 2 * (lane & 3);
            int path = p0 + (col >> 2);
            int dp   = (col & 3) >> 1;
            size_t base = ((size_t)path * N_STEPS + t0 + row) * 2 + dp;
            dst[base]      = make_float2(c[mt][nt][0], c[mt][nt][1]);
            dst[base + 16] = make_float2(c[mt][nt][2], c[mt][nt][3]);
        }
    }
}

// ---------------- kernel 2: single-pass serial scan, 4 paths/block ----------
// 160 threads = (path-local pl 0..3) x (forward n 0..39). Block stages
// fbm4 + dz (cw2 packed into dz.w) for its 4 paths into 64KB dynamic smem,
// then each thread runs the full 512-step scan in ONE pass (reference order).
__global__ __launch_bounds__(PT) void k_path(
    const float* __restrict__ dz,
    const float* __restrict__ F0,
    const float* __restrict__ alphas,
    const float* __restrict__ rhos,
    const float* __restrict__ nus,
    const float* __restrict__ tau,
    const float* __restrict__ L,
    const float* __restrict__ Lam,
    float* __restrict__ out)
{
    extern __shared__ float4 smem[];               // [2][PPB][N_STEPS]
    float4* sfb = smem;                            // fbm4
    float4* sdz = smem + PPB * N_STEPS;            // dz (w = cw2[t])
    __shared__ float som[N_FWD];

    const int u  = threadIdx.x;                    // 0..159
    const int pl = u / N_FWD;                      // 0..3
    const int n  = u - pl * N_FWD;                 // 0..39
    const int p0 = blockIdx.x * PPB;

    // ---- stage: coalesced, 2048 float4 per buffer / 160 threads ----
    const float4* fbg = &g_fbm4[(size_t)p0 * N_STEPS];
    const float4* dzg = (const float4*)dz + (size_t)p0 * N_STEPS;
    for (int i = u; i < PPB * N_STEPS; i += PT) {
        sfb[i] = fbg[i];
        float4 d = dzg[i];
        d.w = g_cw2[i & (N_STEPS - 1)];
        sdz[i] = d;
    }
    if (u < N_FWD) {
        float f0m = F0[u];
        float vsm = alphas[u] * sqrtf(fabsf(f0m + SHIFT));
        som[u] = tau[u] * vsm / (1.f + tau[u] * f0m);
    }

    // ---- per-n constants ----
    float f0n = F0[n];
    float vs  = alphas[n] * sqrtf(fabsf(f0n + SHIFT));
    float rho = rhos[n];
    float nu  = nus[n];
    float sq  = sqrtf(fmaxf(1.f - rho * rho, 0.f));
    float l0 = L[n * 3 + 0], l1 = L[n * 3 + 1], l2 = L[n * 3 + 2];
    float a0 = nu * rho * l0 * LOG2E;
    float a1 = nu * rho * l1 * LOG2E;
    float a2 = nu * rho * l2 * LOG2E;
    float a3 = nu * sq * LOG2E;
    float bb = 0.5f * nu * nu * DT * LOG2E;
    float w0 = vs * l0, w1 = vs * l1, w2 = vs * l2;

    __syncthreads();

    float mdot = 0.f;
    #pragma unroll 8
    for (int m = 0; m < N_FWD; ++m)
        mdot = fmaf(Lam[n * N_FWD + m], som[m], mdot);
    float mu0dt = -vs * mdot * DT;

    // ---- single-pass scan (exact reference accumulation order) ----
    const float4* fbp = sfb + pl * N_STEPS;
    const float4* dzp = sdz + pl * N_STEPS;
    float acc = f0n;
    float* op = out + (size_t)(p0 + pl) * 513 * N_FWD + n;
    __stcs(op, acc);                               // row 0 = F0
    op += N_FWD;
    #pragma unroll 4
    for (int t = 0; t < N_STEPS; ++t) {
        float4 f = fbp[t];
        float4 d = dzp[t];                         // d.w = cw2[t]
        float arg = fmaf(a0, f.x,
                    fmaf(a1, f.y,
                    fmaf(a2, f.z,
                    fmaf(a3, f.w, -bb * d.w))));
        float uv;
        asm("ex2.approx.f32 %0, %1;" : "=f"(uv) : "f"(arg));
        float wr = fmaf(w0, d.x, fmaf(w1, d.y, w2 * d.z));
        acc = fmaf(uv, fmaf(mu0dt, uv, wr), acc);
        __stcs(op, acc);
        op += N_FWD;
    }
}

extern "C" void kernel_launch(void* const* d_in, const int* in_sizes, int n_in,
                              void* d_out, int out_size) {
    const float* dz     = (const float*)d_in[0];
    const float* F0     = (const float*)d_in[1];
    const float* alphas = (const float*)d_in[2];
    const float* rhos   = (const float*)d_in[3];
    const float* nus    = (const float*)d_in[4];
    const float* tau    = (const float*)d_in[5];
    const float* L      = (const float*)d_in[6];
    const float* Lam    = (const float*)d_in[7];
    float* out = (float*)d_out;

    const int smem_bytes = 2 * PPB * N_STEPS * (int)sizeof(float4);   // 64 KB
    cudaFuncSetAttribute(k_path, cudaFuncAttributeMaxDynamicSharedMemorySize, smem_bytes);

    k_conv_mma<<<256, 256>>>(dz);
    k_path<<<N_PATHS / PPB, PT, smem_bytes>>>(dz, F0, alphas, rhos, nus, tau, L, Lam, out);
}

// round 11
// speedup vs baseline: 1.6193x; 1.0216x over previous
#include <cuda_runtime.h>
#include <cuda_bf16.h>
#include <cstdint>

#define N_PATHS 2048
#define N_STEPS 512
#define N_FWD   40
#define DT      (1.0f / 512.0f)
#define SHIFT   0.02f
#define LOG2E   1.4426950408889634f

#define KC      32                    // conv k-chunk
#define SA      36                    // padded row stride (floats)

#define PPB     4                     // paths per block in k_path
#define PT      (PPB * N_FWD)         // 160 threads

// ---------------- device scratch ----------------
__device__ float  g_cw2[N_STEPS];               // inclusive prefix sum of w^2
__device__ float4 g_fbm4[N_PATHS * N_STEPS];    // fbm4[p][t][0..3]

// Toeplitz weight, cancellation-free in fp32:
// w[j] = ((j+1)^0.6 - j^0.6)/0.6 * 2^3.6 / Gamma(0.6)
__device__ __forceinline__ float toeplitz_w(int j) {
    const float scale = 12.125732f / 1.4891922f;
    float num;
    if (j == 0) {
        num = 1.0f / 0.6f;
    } else {
        float fj = (float)j;
        float p6 = exp2f(0.6f * log2f(fj));
        float em = expm1f(0.6f * log1pf(1.0f / fj));
        num = p6 * em * (1.0f / 0.6f);
    }
    return num * scale;
}

__device__ __forceinline__ uint32_t f2tf32(float f) {
    uint32_t u;
    asm("cvt.rna.tf32.f32 %0, %1;" : "=r"(u) : "f"(f));
    return u;
}

__device__ __forceinline__ void mma_tf32(float* c, const uint32_t* a, const uint32_t* b) {
    asm volatile(
        "mma.sync.aligned.m16n8k8.row.col.f32.tf32.tf32.f32 "
        "{%0,%1,%2,%3}, {%4,%5,%6,%7}, {%8,%9}, {%0,%1,%2,%3};"
        : "+f"(c[0]), "+f"(c[1]), "+f"(c[2]), "+f"(c[3])
        : "r"(a[0]), "r"(a[1]), "r"(a[2]), "r"(a[3]), "r"(b[0]), "r"(b[1]));
}

// ---------------- kernel 1: conv as triangular Toeplitz GEMM (tf32 HMMA) ----
// (unchanged from R7)
__global__ __launch_bounds__(256) void k_conv_mma(const float* __restrict__ dz) {
    __shared__ uint32_t sA[128 * SA];
    __shared__ uint32_t sB[128 * SA];
    __shared__ float    swf[N_STEPS];
    __shared__ float    sscan[256];

    const int tid  = threadIdx.x;
    const int wid  = tid >> 5;
    const int lane = tid & 31;
    const int bid  = blockIdx.x;
    const int ti   = 3 - (bid >> 6);     // heavy tiles first
    const int cg   = bid & 63;
    const int p0   = cg * 32;
    const int t0   = 128 * ti;
    const int mw   = (wid >> 2) * 64;
    const int nw   = (wid & 3) * 32;

    for (int i = tid; i < N_STEPS; i += 256) swf[i] = toeplitz_w(i);
    __syncthreads();

    if (bid == 0) {
        float wa = swf[2 * tid], wb = swf[2 * tid + 1];
        float w2b = wb * wb;
        sscan[tid] = wa * wa + w2b;
        __syncthreads();
        #pragma unroll
        for (int off = 1; off < 256; off <<= 1) {
            float v = sscan[tid];
            float u = (tid >= off) ? sscan[tid - off] : 0.f;
            __syncthreads();
            sscan[tid] = v + u;
            __syncthreads();
        }
        float inc = sscan[tid];
        g_cw2[2 * tid + 1] = inc;
        g_cw2[2 * tid]     = inc - w2b;
        __syncthreads();
    }

    float c[4][4][4];
    #pragma unroll
    for (int mt = 0; mt < 4; ++mt)
        #pragma unroll
        for (int nt = 0; nt < 4; ++nt)
            #pragma unroll
            for (int e = 0; e < 4; ++e) c[mt][nt][e] = 0.f;

    const float4* dzv = (const float4*)dz;
    const int n_kc = 4 * ti + 4;

    for (int kc = 0; kc < n_kc; ++kc) {
        const int s0   = KC * kc;
        const int toff = t0 - s0;
        __syncthreads();

        #pragma unroll
        for (int r = 0; r < 16; ++r) {
            int u = tid + 256 * r;
            int i = u >> 5, j = u & 31;
            int q = toff + i - j;
            float v = (q >= 0) ? swf[q] : 0.f;
            sA[i * SA + j] = f2tf32(v);
        }
        #pragma unroll
        for (int r = 0; r < 4; ++r) {
            int u  = tid + 256 * r;
            int pl = u >> 5, k = u & 31;
            float4 x = dzv[(size_t)(p0 + pl) * N_STEPS + s0 + k];
            int n = 4 * pl;
            sB[(n + 0) * SA + k] = f2tf32(x.x);
            sB[(n + 1) * SA + k] = f2tf32(x.y);
            sB[(n + 2) * SA + k] = f2tf32(x.z);
            sB[(n + 3) * SA + k] = f2tf32(x.w);
        }
        __syncthreads();

        #pragma unroll
        for (int ks = 0; ks < 4; ++ks) {
            int kb = 8 * ks;
            uint32_t bf[4][2];
            #pragma unroll
            for (int nt = 0; nt < 4; ++nt) {
                int col = nw + 8 * nt + (lane >> 2);
                bf[nt][0] = sB[col * SA + kb + (lane & 3)];
                bf[nt][1] = sB[col * SA + kb + 4 + (lane & 3)];
            }
            #pragma unroll
            for (int mt = 0; mt < 4; ++mt) {
                int row = mw + 16 * mt + (lane >> 2);
                uint32_t af[4];
                af[0] = sA[row * SA + kb + (lane & 3)];
                af[1] = sA[(row + 8) * SA + kb + (lane & 3)];
                af[2] = sA[row * SA + kb + 4 + (lane & 3)];
                af[3] = sA[(row + 8) * SA + kb + 4 + (lane & 3)];
                #pragma unroll
                for (int nt = 0; nt < 4; ++nt)
                    mma_tf32(c[mt][nt], af, bf[nt]);
            }
        }
    }

    float2* dst = (float2*)g_fbm4;
    #pragma unroll
    for (int mt = 0; mt < 4; ++mt) {
        #pragma unroll
        for (int nt = 0; nt < 4; ++nt) {
            int row  = mw + 16 * mt + (lane >> 2);
            int col  = nw + 8 * nt + 2 * (lane & 3);
            int path = p0 + (col >> 2);
            int dp   = (col & 3) >> 1;
            size_t base = ((size_t)path * N_STEPS + t0 + row) * 2 + dp;
            dst[base]      = make_float2(c[mt][nt][0], c[mt][nt][1]);
            dst[base + 16] = make_float2(c[mt][nt][2], c[mt][nt][3]);
        }
    }
}

// ---------------- kernel 2: single-pass serial scan, 4 paths/block ----------
// 160 threads = (pl 0..3) x (n 0..39). dz+cw2 staged in 32KB shared;
// fbm4 read via LDG (broadcast line per 40-group, MLP from unroll-4).
// 32KB smem -> ~7 blocks/SM -> ~55% occupancy.
__global__ __launch_bounds__(PT) void k_path(
    const float* __restrict__ dz,
    const float* __restrict__ F0,
    const float* __restrict__ alphas,
    const float* __restrict__ rhos,
    const float* __restrict__ nus,
    const float* __restrict__ tau,
    const float* __restrict__ L,
    const float* __restrict__ Lam,
    float* __restrict__ out)
{
    __shared__ float4 sdz[PPB * N_STEPS];          // 32 KB (w slot = cw2[t])
    __shared__ float  som[N_FWD];

    const int u  = threadIdx.x;                    // 0..159
    const int pl = u / N_FWD;                      // 0..3
    const int n  = u - pl * N_FWD;                 // 0..39
    const int p0 = blockIdx.x * PPB;

    // ---- stage dz (+cw2 in .w): coalesced ----
    const float4* dzg = (const float4*)dz + (size_t)p0 * N_STEPS;
    #pragma unroll
    for (int r = 0; r < PPB * N_STEPS / PT + 1; ++r) {
        int i = u + r * PT;
        if (i < PPB * N_STEPS) {
            float4 d = dzg[i];
            d.w = g_cw2[i & (N_STEPS - 1)];
            sdz[i] = d;
        }
    }
    if (u < N_FWD) {
        float f0m = F0[u];
        float vsm = alphas[u] * sqrtf(fabsf(f0m + SHIFT));
        som[u] = tau[u] * vsm / (1.f + tau[u] * f0m);
    }

    // ---- per-n constants ----
    float f0n = F0[n];
    float vs  = alphas[n] * sqrtf(fabsf(f0n + SHIFT));
    float rho = rhos[n];
    float nu  = nus[n];
    float sq  = sqrtf(fmaxf(1.f - rho * rho, 0.f));
    float l0 = L[n * 3 + 0], l1 = L[n * 3 + 1], l2 = L[n * 3 + 2];
    float a0 = nu * rho * l0 * LOG2E;
    float a1 = nu * rho * l1 * LOG2E;
    float a2 = nu * rho * l2 * LOG2E;
    float a3 = nu * sq * LOG2E;
    float bb = 0.5f * nu * nu * DT * LOG2E;
    float w0 = vs * l0, w1 = vs * l1, w2 = vs * l2;

    __syncthreads();

    float mdot = 0.f;
    #pragma unroll 8
    for (int m = 0; m < N_FWD; ++m)
        mdot = fmaf(Lam[n * N_FWD + m], som[m], mdot);
    float mu0dt = -vs * mdot * DT;

    // ---- single-pass scan (exact reference accumulation order) ----
    const float4* fbp = &g_fbm4[(size_t)(p0 + pl) * N_STEPS];
    const float4* dzp = sdz + pl * N_STEPS;
    float acc = f0n;
    float* op = out + (size_t)(p0 + pl) * 513 * N_FWD + n;
    __stcs(op, acc);                               // row 0 = F0
    op += N_FWD;

    #pragma unroll 1
    for (int tb = 0; tb < N_STEPS; tb += 4) {
        // 4 independent fb loads (MLP), then 4 dependent scan steps
        float4 f0 = __ldg(&fbp[tb + 0]);
        float4 f1 = __ldg(&fbp[tb + 1]);
        float4 f2 = __ldg(&fbp[tb + 2]);
        float4 f3 = __ldg(&fbp[tb + 3]);
        #pragma unroll
        for (int i = 0; i < 4; ++i) {
            float4 f = (i == 0) ? f0 : (i == 1) ? f1 : (i == 2) ? f2 : f3;
            float4 d = dzp[tb + i];                // d.w = cw2[t]
            float arg = fmaf(a0, f.x,
                        fmaf(a1, f.y,
                        fmaf(a2, f.z,
                        fmaf(a3, f.w, -bb * d.w))));
            float uv;
            asm("ex2.approx.f32 %0, %1;" : "=f"(uv) : "f"(arg));
            float wr = fmaf(w0, d.x, fmaf(w1, d.y, w2 * d.z));
            acc = fmaf(uv, fmaf(mu0dt, uv, wr), acc);
            __stcs(op, acc);
            op += N_FWD;
        }
    }
}

extern "C" void kernel_launch(void* const* d_in, const int* in_sizes, int n_in,
                              void* d_out, int out_size) {
    const float* dz     = (const float*)d_in[0];
    const float* F0     = (const float*)d_in[1];
    const float* alphas = (const float*)d_in[2];
    const float* rhos   = (const float*)d_in[3];
    const float* nus    = (const float*)d_in[4];
    const float* tau    = (const float*)d_in[5];
    const float* L      = (const float*)d_in[6];
    const float* Lam    = (const float*)d_in[7];
    float* out = (float*)d_out;

    k_conv_mma<<<256, 256>>>(dz);
    k_path<<<N_PATHS / PPB, PT>>>(dz, F0, alphas, rhos, nus, tau, L, Lam, out);
}

// round 12
// speedup vs baseline: 1.6264x; 1.0044x over previous
#include <cuda_runtime.h>
#include <cuda_bf16.h>
#include <cstdint>

#define N_PATHS 2048
#define N_STEPS 512
#define N_FWD   40
#define DT      (1.0f / 512.0f)
#define SHIFT   0.02f
#define LOG2E   1.4426950408889634f

#define KC      32                    // conv k-chunk
#define SA      36                    // padded row stride (floats)

#define PPB     4                     // paths per block in k_path
#define PT      (PPB * N_FWD)         // 160 threads

// ---------------- device scratch ----------------
__device__ float  g_cw2[N_STEPS];               // inclusive prefix sum of w^2
__device__ float4 g_fbm4[N_PATHS * N_STEPS];    // fbm4[p][t][0..3]

// Toeplitz weight, cancellation-free in fp32:
// w[j] = ((j+1)^0.6 - j^0.6)/0.6 * 2^3.6 / Gamma(0.6)
__device__ __forceinline__ float toeplitz_w(int j) {
    const float scale = 12.125732f / 1.4891922f;
    float num;
    if (j == 0) {
        num = 1.0f / 0.6f;
    } else {
        float fj = (float)j;
        float p6 = exp2f(0.6f * log2f(fj));
        float em = expm1f(0.6f * log1pf(1.0f / fj));
        num = p6 * em * (1.0f / 0.6f);
    }
    return num * scale;
}

__device__ __forceinline__ uint32_t f2tf32(float f) {
    uint32_t u;
    asm("cvt.rna.tf32.f32 %0, %1;" : "=r"(u) : "f"(f));
    return u;
}

__device__ __forceinline__ void mma_tf32(float* c, const uint32_t* a, const uint32_t* b) {
    asm volatile(
        "mma.sync.aligned.m16n8k8.row.col.f32.tf32.tf32.f32 "
        "{%0,%1,%2,%3}, {%4,%5,%6,%7}, {%8,%9}, {%0,%1,%2,%3};"
        : "+f"(c[0]), "+f"(c[1]), "+f"(c[2]), "+f"(c[3])
        : "r"(a[0]), "r"(a[1]), "r"(a[2]), "r"(a[3]), "r"(b[0]), "r"(b[1]));
}

// ---------------- kernel 1: conv as triangular Toeplitz GEMM (tf32 HMMA) ----
// (unchanged from R7)
__global__ __launch_bounds__(256) void k_conv_mma(const float* __restrict__ dz) {
    __shared__ uint32_t sA[128 * SA];
    __shared__ uint32_t sB[128 * SA];
    __shared__ float    swf[N_STEPS];
    __shared__ float    sscan[256];

    const int tid  = threadIdx.x;
    const int wid  = tid >> 5;
    const int lane = tid & 31;
    const int bid  = blockIdx.x;
    const int ti   = 3 - (bid >> 6);     // heavy tiles first
    const int cg   = bid & 63;
    const int p0   = cg * 32;
    const int t0   = 128 * ti;
    const int mw   = (wid >> 2) * 64;
    const int nw   = (wid & 3) * 32;

    for (int i = tid; i < N_STEPS; i += 256) swf[i] = toeplitz_w(i);
    __syncthreads();

    if (bid == 0) {
        float wa = swf[2 * tid], wb = swf[2 * tid + 1];
        float w2b = wb * wb;
        sscan[tid] = wa * wa + w2b;
        __syncthreads();
        #pragma unroll
        for (int off = 1; off < 256; off <<= 1) {
            float v = sscan[tid];
            float u = (tid >= off) ? sscan[tid - off] : 0.f;
            __syncthreads();
            sscan[tid] = v + u;
            __syncthreads();
        }
        float inc = sscan[tid];
        g_cw2[2 * tid + 1] = inc;
        g_cw2[2 * tid]     = inc - w2b;
        __syncthreads();
    }

    float c[4][4][4];
    #pragma unroll
    for (int mt = 0; mt < 4; ++mt)
        #pragma unroll
        for (int nt = 0; nt < 4; ++nt)
            #pragma unroll
            for (int e = 0; e < 4; ++e) c[mt][nt][e] = 0.f;

    const float4* dzv = (const float4*)dz;
    const int n_kc = 4 * ti + 4;

    for (int kc = 0; kc < n_kc; ++kc) {
        const int s0   = KC * kc;
        const int toff = t0 - s0;
        __syncthreads();

        #pragma unroll
        for (int r = 0; r < 16; ++r) {
            int u = tid + 256 * r;
            int i = u >> 5, j = u & 31;
            int q = toff + i - j;
            float v = (q >= 0) ? swf[q] : 0.f;
            sA[i * SA + j] = f2tf32(v);
        }
        #pragma unroll
        for (int r = 0; r < 4; ++r) {
            int u  = tid + 256 * r;
            int pl = u >> 5, k = u & 31;
            float4 x = dzv[(size_t)(p0 + pl) * N_STEPS + s0 + k];
            int n = 4 * pl;
            sB[(n + 0) * SA + k] = f2tf32(x.x);
            sB[(n + 1) * SA + k] = f2tf32(x.y);
            sB[(n + 2) * SA + k] = f2tf32(x.z);
            sB[(n + 3) * SA + k] = f2tf32(x.w);
        }
        __syncthreads();

        #pragma unroll
        for (int ks = 0; ks < 4; ++ks) {
            int kb = 8 * ks;
            uint32_t bf[4][2];
            #pragma unroll
            for (int nt = 0; nt < 4; ++nt) {
                int col = nw + 8 * nt + (lane >> 2);
                bf[nt][0] = sB[col * SA + kb + (lane & 3)];
                bf[nt][1] = sB[col * SA + kb + 4 + (lane & 3)];
            }
            #pragma unroll
            for (int mt = 0; mt < 4; ++mt) {
                int row = mw + 16 * mt + (lane >> 2);
                uint32_t af[4];
                af[0] = sA[row * SA + kb + (lane & 3)];
                af[1] = sA[(row + 8) * SA + kb + (lane & 3)];
                af[2] = sA[row * SA + kb + 4 + (lane & 3)];
                af[3] = sA[(row + 8) * SA + kb + 4 + (lane & 3)];
                #pragma unroll
                for (int nt = 0; nt < 4; ++nt)
                    mma_tf32(c[mt][nt], af, bf[nt]);
            }
        }
    }

    float2* dst = (float2*)g_fbm4;
    #pragma unroll
    for (int mt = 0; mt < 4; ++mt) {
        #pragma unroll
        for (int nt = 0; nt < 4; ++nt) {
            int row  = mw + 16 * mt + (lane >> 2);
            int col  = nw + 8 * nt + 2 * (lane & 3);
            int path = p0 + (col >> 2);
            int dp   = (col & 3) >> 1;
            size_t base = ((size_t)path * N_STEPS + t0 + row) * 2 + dp;
            dst[base]      = make_float2(c[mt][nt][0], c[mt][nt][1]);
            dst[base + 16] = make_float2(c[mt][nt][2], c[mt][nt][3]);
        }
    }
}

// ---------------- kernel 2: single-pass scan, smem-staged, SW-pipelined -----
// 160 threads = (pl 0..3) x (n 0..39). fb+dz (cw2 in .w) staged in 64KB
// dynamic smem (R10 config). Inner loop double-buffers 4-iteration register
// batches so LDS latency overlaps compute; regs free to grow (smem caps
// residency at 3 blocks anyway).
__global__ __launch_bounds__(PT, 3) void k_path(
    const float* __restrict__ dz,
    const float* __restrict__ F0,
    const float* __restrict__ alphas,
    const float* __restrict__ rhos,
    const float* __restrict__ nus,
    const float* __restrict__ tau,
    const float* __restrict__ L,
    const float* __restrict__ Lam,
    float* __restrict__ out)
{
    extern __shared__ float4 smem[];               // [2][PPB][N_STEPS] = 64 KB
    float4* sfb = smem;
    float4* sdz = smem + PPB * N_STEPS;
    __shared__ float som[N_FWD];

    const int u  = threadIdx.x;                    // 0..159
    const int pl = u / N_FWD;                      // 0..3
    const int n  = u - pl * N_FWD;                 // 0..39
    const int p0 = blockIdx.x * PPB;

    // ---- stage: coalesced ----
    const float4* fbg = &g_fbm4[(size_t)p0 * N_STEPS];
    const float4* dzg = (const float4*)dz + (size_t)p0 * N_STEPS;
    for (int i = u; i < PPB * N_STEPS; i += PT) {
        sfb[i] = fbg[i];
        float4 d = dzg[i];
        d.w = g_cw2[i & (N_STEPS - 1)];
        sdz[i] = d;
    }
    if (u < N_FWD) {
        float f0m = F0[u];
        float vsm = alphas[u] * sqrtf(fabsf(f0m + SHIFT));
        som[u] = tau[u] * vsm / (1.f + tau[u] * f0m);
    }

    // ---- per-n constants ----
    float f0n = F0[n];
    float vs  = alphas[n] * sqrtf(fabsf(f0n + SHIFT));
    float rho = rhos[n];
    float nu  = nus[n];
    float sq  = sqrtf(fmaxf(1.f - rho * rho, 0.f));
    float l0 = L[n * 3 + 0], l1 = L[n * 3 + 1], l2 = L[n * 3 + 2];
    float a0 = nu * rho * l0 * LOG2E;
    float a1 = nu * rho * l1 * LOG2E;
    float a2 = nu * rho * l2 * LOG2E;
    float a3 = nu * sq * LOG2E;
    float bb = 0.5f * nu * nu * DT * LOG2E;
    float w0 = vs * l0, w1 = vs * l1, w2 = vs * l2;

    __syncthreads();

    float mdot = 0.f;
    #pragma unroll 8
    for (int m = 0; m < N_FWD; ++m)
        mdot = fmaf(Lam[n * N_FWD + m], som[m], mdot);
    float mu0dt = -vs * mdot * DT;

    // ---- single-pass scan, double-buffered 4-iter register batches ----
    const float4* fbp = sfb + pl * N_STEPS;
    const float4* dzp = sdz + pl * N_STEPS;
    float acc = f0n;
    float* op = out + (size_t)(p0 + pl) * 513 * N_FWD + n;
    __stcs(op, acc);                               // row 0 = F0
    op += N_FWD;

    float4 fR[4], dR[4], fN[4], dN[4];
    #pragma unroll
    for (int i = 0; i < 4; ++i) { fR[i] = fbp[i]; dR[i] = dzp[i]; }

    #pragma unroll 2
    for (int tb = 0; tb < N_STEPS; tb += 4) {
        // prefetch next batch while computing current
        if (tb + 4 < N_STEPS) {
            #pragma unroll
            for (int i = 0; i < 4; ++i) {
                fN[i] = fbp[tb + 4 + i];
                dN[i] = dzp[tb + 4 + i];
            }
        }
        #pragma unroll
        for (int i = 0; i < 4; ++i) {
            float4 f = fR[i];
            float4 d = dR[i];                      // d.w = cw2[t]
            float arg = fmaf(a0, f.x,
                        fmaf(a1, f.y,
                        fmaf(a2, f.z,
                        fmaf(a3, f.w, -bb * d.w))));
            float uv;
            asm("ex2.approx.f32 %0, %1;" : "=f"(uv) : "f"(arg));
            float wr = fmaf(w0, d.x, fmaf(w1, d.y, w2 * d.z));
            acc = fmaf(uv, fmaf(mu0dt, uv, wr), acc);
            __stcs(op, acc);
            op += N_FWD;
        }
        #pragma unroll
        for (int i = 0; i < 4; ++i) { fR[i] = fN[i]; dR[i] = dN[i]; }
    }
}

extern "C" void kernel_launch(void* const* d_in, const int* in_sizes, int n_in,
                              void* d_out, int out_size) {
    const float* dz     = (const float*)d_in[0];
    const float* F0     = (const float*)d_in[1];
    const float* alphas = (const float*)d_in[2];
    const float* rhos   = (const float*)d_in[3];
    const float* nus    = (const float*)d_in[4];
    const float* tau    = (const float*)d_in[5];
    const float* L      = (const float*)d_in[6];
    const float* Lam    = (const float*)d_in[7];
    float* out = (float*)d_out;

    const int smem_bytes = 2 * PPB * N_STEPS * (int)sizeof(float4);   // 64 KB
    cudaFuncSetAttribute(k_path, cudaFuncAttributeMaxDynamicSharedMemorySize, smem_bytes);

    k_conv_mma<<<256, 256>>>(dz);
    k_path<<<N_PATHS / PPB, PT, smem_bytes>>>(dz, F0, alphas, rhos, nus, tau, L, Lam, out);
}

// round 13
// speedup vs baseline: 1.6924x; 1.0406x over previous
#include <cuda_runtime.h>
#include <cuda_bf16.h>
#include <cstdint>

#define N_PATHS 2048
#define N_STEPS 512
#define N_FWD   40
#define DT      (1.0f / 512.0f)
#define SHIFT   0.02f
#define LOG2E   1.4426950408889634f

#define KC      32                    // conv k-chunk
#define SA      36                    // padded row stride (floats)

#define PPB     4                     // paths per block in k_path
#define PT      (PPB * N_FWD)         // 160 threads

// ---------------- device scratch ----------------
__device__ float  g_cw2[N_STEPS];               // inclusive prefix sum of w^2
__device__ float4 g_fbm4[N_PATHS * N_STEPS];    // fbm4[p][t][0..3]

// Toeplitz weight, cancellation-free in fp32:
// w[j] = ((j+1)^0.6 - j^0.6)/0.6 * 2^3.6 / Gamma(0.6)
__device__ __forceinline__ float toeplitz_w(int j) {
    const float scale = 12.125732f / 1.4891922f;
    float num;
    if (j == 0) {
        num = 1.0f / 0.6f;
    } else {
        float fj = (float)j;
        float p6 = exp2f(0.6f * log2f(fj));
        float em = expm1f(0.6f * log1pf(1.0f / fj));
        num = p6 * em * (1.0f / 0.6f);
    }
    return num * scale;
}

__device__ __forceinline__ uint32_t f2tf32(float f) {
    uint32_t u;
    asm("cvt.rna.tf32.f32 %0, %1;" : "=r"(u) : "f"(f));
    return u;
}

__device__ __forceinline__ void mma_tf32(float* c, const uint32_t* a, const uint32_t* b) {
    asm volatile(
        "mma.sync.aligned.m16n8k8.row.col.f32.tf32.tf32.f32 "
        "{%0,%1,%2,%3}, {%4,%5,%6,%7}, {%8,%9}, {%0,%1,%2,%3};"
        : "+f"(c[0]), "+f"(c[1]), "+f"(c[2]), "+f"(c[3])
        : "r"(a[0]), "r"(a[1]), "r"(a[2]), "r"(a[3]), "r"(b[0]), "r"(b[1]));
}

// ---------------- kernel 1: conv as triangular Toeplitz GEMM (tf32 HMMA) ----
// (unchanged from R7)
__global__ __launch_bounds__(256) void k_conv_mma(const float* __restrict__ dz) {
    __shared__ uint32_t sA[128 * SA];
    __shared__ uint32_t sB[128 * SA];
    __shared__ float    swf[N_STEPS];
    __shared__ float    sscan[256];

    const int tid  = threadIdx.x;
    const int wid  = tid >> 5;
    const int lane = tid & 31;
    const int bid  = blockIdx.x;
    const int ti   = 3 - (bid >> 6);     // heavy tiles first
    const int cg   = bid & 63;
    const int p0   = cg * 32;
    const int t0   = 128 * ti;
    const int mw   = (wid >> 2) * 64;
    const int nw   = (wid & 3) * 32;

    for (int i = tid; i < N_STEPS; i += 256) swf[i] = toeplitz_w(i);
    __syncthreads();

    if (bid == 0) {
        float wa = swf[2 * tid], wb = swf[2 * tid + 1];
        float w2b = wb * wb;
        sscan[tid] = wa * wa + w2b;
        __syncthreads();
        #pragma unroll
        for (int off = 1; off < 256; off <<= 1) {
            float v = sscan[tid];
            float u = (tid >= off) ? sscan[tid - off] : 0.f;
            __syncthreads();
            sscan[tid] = v + u;
            __syncthreads();
        }
        float inc = sscan[tid];
        g_cw2[2 * tid + 1] = inc;
        g_cw2[2 * tid]     = inc - w2b;
        __syncthreads();
    }

    float c[4][4][4];
    #pragma unroll
    for (int mt = 0; mt < 4; ++mt)
        #pragma unroll
        for (int nt = 0; nt < 4; ++nt)
            #pragma unroll
            for (int e = 0; e < 4; ++e) c[mt][nt][e] = 0.f;

    const float4* dzv = (const float4*)dz;
    const int n_kc = 4 * ti + 4;

    for (int kc = 0; kc < n_kc; ++kc) {
        const int s0   = KC * kc;
        const int toff = t0 - s0;
        __syncthreads();

        #pragma unroll
        for (int r = 0; r < 16; ++r) {
            int u = tid + 256 * r;
            int i = u >> 5, j = u & 31;
            int q = toff + i - j;
            float v = (q >= 0) ? swf[q] : 0.f;
            sA[i * SA + j] = f2tf32(v);
        }
        #pragma unroll
        for (int r = 0; r < 4; ++r) {
            int u  = tid + 256 * r;
            int pl = u >> 5, k = u & 31;
            float4 x = dzv[(size_t)(p0 + pl) * N_STEPS + s0 + k];
            int n = 4 * pl;
            sB[(n + 0) * SA + k] = f2tf32(x.x);
            sB[(n + 1) * SA + k] = f2tf32(x.y);
            sB[(n + 2) * SA + k] = f2tf32(x.z);
            sB[(n + 3) * SA + k] = f2tf32(x.w);
        }
        __syncthreads();

        #pragma unroll
        for (int ks = 0; ks < 4; ++ks) {
            int kb = 8 * ks;
            uint32_t bf[4][2];
            #pragma unroll
            for (int nt = 0; nt < 4; ++nt) {
                int col = nw + 8 * nt + (lane >> 2);
                bf[nt][0] = sB[col * SA + kb + (lane & 3)];
                bf[nt][1] = sB[col * SA + kb + 4 + (lane & 3)];
            }
            #pragma unroll
            for (int mt = 0; mt < 4; ++mt) {
                int row = mw + 16 * mt + (lane >> 2);
                uint32_t af[4];
                af[0] = sA[row * SA + kb + (lane & 3)];
                af[1] = sA[(row + 8) * SA + kb + (lane & 3)];
                af[2] = sA[row * SA + kb + 4 + (lane & 3)];
                af[3] = sA[(row + 8) * SA + kb + 4 + (lane & 3)];
                #pragma unroll
                for (int nt = 0; nt < 4; ++nt)
                    mma_tf32(c[mt][nt], af, bf[nt]);
            }
        }
    }

    float2* dst = (float2*)g_fbm4;
    #pragma unroll
    for (int mt = 0; mt < 4; ++mt) {
        #pragma unroll
        for (int nt = 0; nt < 4; ++nt) {
            int row  = mw + 16 * mt + (lane >> 2);
            int col  = nw + 8 * nt + 2 * (lane & 3);
            int path = p0 + (col >> 2);
            int dp   = (col & 3) >> 1;
            size_t base = ((size_t)path * N_STEPS + t0 + row) * 2 + dp;
            dst[base]      = make_float2(c[mt][nt][0], c[mt][nt][1]);
            dst[base + 16] = make_float2(c[mt][nt][2], c[mt][nt][3]);
        }
    }
}

// ---------------- kernel 2: single-pass scan, two-bank pipeline, no copies --
__global__ __launch_bounds__(PT, 3) void k_path(
    const float* __restrict__ dz,
    const float* __restrict__ F0,
    const float* __restrict__ alphas,
    const float* __restrict__ rhos,
    const float* __restrict__ nus,
    const float* __restrict__ tau,
    const float* __restrict__ L,
    const float* __restrict__ Lam,
    float* __restrict__ out)
{
    extern __shared__ float4 smem[];               // [2][PPB][N_STEPS] = 64 KB
    float4* sfb = smem;
    float4* sdz = smem + PPB * N_STEPS;
    __shared__ float som[N_FWD];

    const int u  = threadIdx.x;                    // 0..159
    const int pl = u / N_FWD;                      // 0..3
    const int n  = u - pl * N_FWD;                 // 0..39
    const int p0 = blockIdx.x * PPB;

    // ---- stage: coalesced ----
    const float4* fbg = &g_fbm4[(size_t)p0 * N_STEPS];
    const float4* dzg = (const float4*)dz + (size_t)p0 * N_STEPS;
    for (int i = u; i < PPB * N_STEPS; i += PT) {
        sfb[i] = fbg[i];
        float4 d = dzg[i];
        d.w = g_cw2[i & (N_STEPS - 1)];
        sdz[i] = d;
    }
    if (u < N_FWD) {
        float f0m = F0[u];
        float vsm = alphas[u] * sqrtf(fabsf(f0m + SHIFT));
        som[u] = tau[u] * vsm / (1.f + tau[u] * f0m);
    }

    // ---- per-n constants ----
    float f0n = F0[n];
    float vs  = alphas[n] * sqrtf(fabsf(f0n + SHIFT));
    float rho = rhos[n];
    float nu  = nus[n];
    float sq  = sqrtf(fmaxf(1.f - rho * rho, 0.f));
    float l0 = L[n * 3 + 0], l1 = L[n * 3 + 1], l2 = L[n * 3 + 2];
    float a0 = nu * rho * l0 * LOG2E;
    float a1 = nu * rho * l1 * LOG2E;
    float a2 = nu * rho * l2 * LOG2E;
    float a3 = nu * sq * LOG2E;
    float bb = 0.5f * nu * nu * DT * LOG2E;
    float w0 = vs * l0, w1 = vs * l1, w2 = vs * l2;

    __syncthreads();

    float mdot = 0.f;
    #pragma unroll 8
    for (int m = 0; m < N_FWD; ++m)
        mdot = fmaf(Lam[n * N_FWD + m], som[m], mdot);
    float mu0dt = -vs * mdot * DT;

    // ---- single-pass scan: two banks, loads write registers directly ----
    const float4* fbp = sfb + pl * N_STEPS;
    const float4* dzp = sdz + pl * N_STEPS;
    float acc = f0n;
    float* op = out + (size_t)(p0 + pl) * 513 * N_FWD + n;
    __stcs(op, acc);                               // row 0 = F0
    op += N_FWD;

#define SCAN_STEP(fv, dv)                                         \
    do {                                                          \
        float arg = fmaf(a0, (fv).x,                              \
                    fmaf(a1, (fv).y,                              \
                    fmaf(a2, (fv).z,                              \
                    fmaf(a3, (fv).w, -bb * (dv).w))));            \
        float uv;                                                 \
        asm("ex2.approx.f32 %0, %1;" : "=f"(uv) : "f"(arg));      \
        float wr = fmaf(w0, (dv).x, fmaf(w1, (dv).y, w2 * (dv).z)); \
        acc = fmaf(uv, fmaf(mu0dt, uv, wr), acc);                 \
        __stcs(op, acc);                                          \
        op += N_FWD;                                              \
    } while (0)

    float4 fA[4], dA[4], fB[4], dB[4];
    #pragma unroll
    for (int i = 0; i < 4; ++i) { fA[i] = fbp[i]; dA[i] = dzp[i]; }

    #pragma unroll 1
    for (int tb = 0; tb < N_STEPS; tb += 8) {
        #pragma unroll
        for (int i = 0; i < 4; ++i) { fB[i] = fbp[tb + 4 + i]; dB[i] = dzp[tb + 4 + i]; }
        #pragma unroll
        for (int i = 0; i < 4; ++i) SCAN_STEP(fA[i], dA[i]);
        if (tb + 8 < N_STEPS) {
            #pragma unroll
            for (int i = 0; i < 4; ++i) { fA[i] = fbp[tb + 8 + i]; dA[i] = dzp[tb + 8 + i]; }
        }
        #pragma unroll
        for (int i = 0; i < 4; ++i) SCAN_STEP(fB[i], dB[i]);
    }
#undef SCAN_STEP
}

extern "C" void kernel_launch(void* const* d_in, const int* in_sizes, int n_in,
                              void* d_out, int out_size) {
    const float* dz     = (const float*)d_in[0];
    const float* F0     = (const float*)d_in[1];
    const float* alphas = (const float*)d_in[2];
    const float* rhos   = (const float*)d_in[3];
    const float* nus    = (const float*)d_in[4];
    const float* tau    = (const float*)d_in[5];
    const float* L      = (const float*)d_in[6];
    const float* Lam    = (const float*)d_in[7];
    float* out = (float*)d_out;

    const int smem_bytes = 2 * PPB * N_STEPS * (int)sizeof(float4);   // 64 KB
    cudaFuncSetAttribute(k_path, cudaFuncAttributeMaxDynamicSharedMemorySize, smem_bytes);

    k_conv_mma<<<256, 256>>>(dz);
    k_path<<<N_PATHS / PPB, PT, smem_bytes>>>(dz, F0, alphas, rhos, nus, tau, L, Lam, out);
}

// round 15
// speedup vs baseline: 1.8614x; 1.0998x over previous
#include <cuda_runtime.h>
#include <cuda_bf16.h>
#include <cstdint>

#define N_PATHS 2048
#define N_STEPS 512
#define N_FWD   40
#define DT      (1.0f / 512.0f)
#define SHIFT   0.02f
#define LOG2E   1.4426950408889634f

#define KC      32                    // conv k-chunk
#define SA      36                    // padded row stride (floats)
#define TILE_U  (128 * SA)            // uint32s per B tile
#define E_ROWS  608                   // extended band rows (max, ti=3)

#define PPB     4                     // paths per block in k_path
#define PT      (PPB * N_FWD)         // 160 threads

// ---------------- device scratch ----------------
__device__ float  g_cw2[N_STEPS];               // inclusive prefix sum of w^2
__device__ float4 g_fbm4[N_PATHS * N_STEPS];    // fbm4[p][t][0..3]

// Toeplitz weight, cancellation-free in fp32:
// w[j] = ((j+1)^0.6 - j^0.6)/0.6 * 2^3.6 / Gamma(0.6)
__device__ __forceinline__ float toeplitz_w(int j) {
    const float scale = 12.125732f / 1.4891922f;
    float num;
    if (j == 0) {
        num = 1.0f / 0.6f;
    } else {
        float fj = (float)j;
        float p6 = exp2f(0.6f * log2f(fj));
        float em = expm1f(0.6f * log1pf(1.0f / fj));
        num = p6 * em * (1.0f / 0.6f);
    }
    return num * scale;
}

__device__ __forceinline__ void mma_tf32(float* c, const uint32_t* a, const uint32_t* b) {
    asm volatile(
        "mma.sync.aligned.m16n8k8.row.col.f32.tf32.tf32.f32 "
        "{%0,%1,%2,%3}, {%4,%5,%6,%7}, {%8,%9}, {%0,%1,%2,%3};"
        : "+f"(c[0]), "+f"(c[1]), "+f"(c[2]), "+f"(c[3])
        : "r"(a[0]), "r"(a[1]), "r"(a[2]), "r"(a[3]), "r"(b[0]), "r"(b[1]));
}

// ---------------- kernel 1: triangular Toeplitz GEMM (tf32 HMMA) ------------
// Extended-band A: E[r][j] = w[r - 96 - j] staged ONCE; chunk kc's A tile is
// the window starting at row BIAS - 32*kc (pure pointer offset).
// B double-buffered: register prefetch overlaps MMA; one barrier per chunk.
// Raw fp32 bits into HMMA.TF32 (HW truncates mantissa).
__global__ __launch_bounds__(256) void k_conv_mma(const float* __restrict__ dz) {
    extern __shared__ uint32_t dsm[];
    uint32_t* sE    = dsm;                              // E_ROWS * SA
    uint32_t* sB    = dsm + E_ROWS * SA;                // 2 * TILE_U
    float*    swf   = (float*)(sB + 2 * TILE_U);        // 512
    float*    sscan = swf + N_STEPS;                    // 256

    const int tid  = threadIdx.x;
    const int wid  = tid >> 5;
    const int lane = tid & 31;
    const int bid  = blockIdx.x;
    const int ti   = 3 - (bid >> 6);     // heavy tiles first
    const int cg   = bid & 63;
    const int p0   = cg * 32;
    const int t0   = 128 * ti;
    const int mw   = (wid >> 2) * 64;
    const int nw   = (wid & 3) * 32;

    const int n_kc = 4 * ti + 4;
    const int BIAS = 32 * (n_kc - 1);    // = 128*ti + 96
    const int rows = 128 + BIAS;         // E rows needed by this CTA

    for (int i = tid; i < N_STEPS; i += 256) swf[i] = toeplitz_w(i);
    __syncthreads();

    if (bid == 0) {
        float wa = swf[2 * tid], wb = swf[2 * tid + 1];
        float w2b = wb * wb;
        sscan[tid] = wa * wa + w2b;
        __syncthreads();
        #pragma unroll
        for (int off = 1; off < 256; off <<= 1) {
            float v = sscan[tid];
            float u = (tid >= off) ? sscan[tid - off] : 0.f;
            __syncthreads();
            sscan[tid] = v + u;
            __syncthreads();
        }
        float inc = sscan[tid];
        g_cw2[2 * tid + 1] = inc;
        g_cw2[2 * tid]     = inc - w2b;
        __syncthreads();
    }

    // ---- stage extended band E once: E[r][j] = w[r - 96 - j] (0 if q<0) ----
    // q max = rows-1 - 96 = 128*ti + 127 <= 511, so only q>=0 guard needed.
    for (int idx = tid; idx < rows * KC; idx += 256) {
        int r = idx >> 5, j = idx & 31;
        int q = r - 96 - j;
        float v = (q >= 0) ? swf[q] : 0.f;
        sE[r * SA + j] = __float_as_uint(v);
    }

    const float4* dzv = (const float4*)dz;

    // ---- stage B chunk 0 ----
    #pragma unroll
    for (int r = 0; r < 4; ++r) {
        int u2 = tid + 256 * r;
        int pl = u2 >> 5, k = u2 & 31;
        float4 x = dzv[(size_t)(p0 + pl) * N_STEPS + k];
        int nn = 4 * pl;
        sB[(nn + 0) * SA + k] = __float_as_uint(x.x);
        sB[(nn + 1) * SA + k] = __float_as_uint(x.y);
        sB[(nn + 2) * SA + k] = __float_as_uint(x.z);
        sB[(nn + 3) * SA + k] = __float_as_uint(x.w);
    }
    __syncthreads();

    float c[4][4][4];
    #pragma unroll
    for (int mt = 0; mt < 4; ++mt)
        #pragma unroll
        for (int nt = 0; nt < 4; ++nt)
            #pragma unroll
            for (int e = 0; e < 4; ++e) c[mt][nt][e] = 0.f;

    for (int kc = 0; kc < n_kc; ++kc) {
        const uint32_t* Acur = sE + (BIAS - 32 * kc) * SA;   // window into E
        const uint32_t* Bcur = sB + (kc & 1) * TILE_U;
        uint32_t*       Bnxt = sB + ((kc + 1) & 1) * TILE_U;
        const bool pref = (kc + 1 < n_kc);

        // prefetch next B chunk into registers (overlaps MMA)
        float4 xr[4];
        if (pref) {
            int s0n = KC * (kc + 1);
            #pragma unroll
            for (int r = 0; r < 4; ++r) {
                int u2 = tid + 256 * r;
                int pl = u2 >> 5, k = u2 & 31;
                xr[r] = dzv[(size_t)(p0 + pl) * N_STEPS + s0n + k];
            }
        }

        // compute: 4 k8-steps
        #pragma unroll
        for (int ks = 0; ks < 4; ++ks) {
            int kb = 8 * ks;
            uint32_t bf[4][2];
            #pragma unroll
            for (int nt = 0; nt < 4; ++nt) {
                int col = nw + 8 * nt + (lane >> 2);
                bf[nt][0] = Bcur[col * SA + kb + (lane & 3)];
                bf[nt][1] = Bcur[col * SA + kb + 4 + (lane & 3)];
            }
            #pragma unroll
            for (int mt = 0; mt < 4; ++mt) {
                int row = mw + 16 * mt + (lane >> 2);
                uint32_t af[4];
                af[0] = Acur[row * SA + kb + (lane & 3)];
                af[1] = Acur[(row + 8) * SA + kb + (lane & 3)];
                af[2] = Acur[row * SA + kb + 4 + (lane & 3)];
                af[3] = Acur[(row + 8) * SA + kb + 4 + (lane & 3)];
                #pragma unroll
                for (int nt = 0; nt < 4; ++nt)
                    mma_tf32(c[mt][nt], af, bf[nt]);
            }
        }

        // commit prefetched chunk
        if (pref) {
            #pragma unroll
            for (int r = 0; r < 4; ++r) {
                int u2 = tid + 256 * r;
                int pl = u2 >> 5, k = u2 & 31;
                int nn = 4 * pl;
                Bnxt[(nn + 0) * SA + k] = __float_as_uint(xr[r].x);
                Bnxt[(nn + 1) * SA + k] = __float_as_uint(xr[r].y);
                Bnxt[(nn + 2) * SA + k] = __float_as_uint(xr[r].z);
                Bnxt[(nn + 3) * SA + k] = __float_as_uint(xr[r].w);
            }
        }
        __syncthreads();
    }

    float2* dst = (float2*)g_fbm4;
    #pragma unroll
    for (int mt = 0; mt < 4; ++mt) {
        #pragma unroll
        for (int nt = 0; nt < 4; ++nt) {
            int row  = mw + 16 * mt + (lane >> 2);
            int col  = nw + 8 * nt + 2 * (lane & 3);
            int path = p0 + (col >> 2);
            int dp   = (col & 3) >> 1;
            size_t base = ((size_t)path * N_STEPS + t0 + row) * 2 + dp;
            dst[base]      = make_float2(c[mt][nt][0], c[mt][nt][1]);
            dst[base + 16] = make_float2(c[mt][nt][2], c[mt][nt][3]);
        }
    }
}

// ---------------- kernel 2: single-pass scan, two-bank pipeline (R13) -------
__global__ __launch_bounds__(PT, 3) void k_path(
    const float* __restrict__ dz,
    const float* __restrict__ F0,
    const float* __restrict__ alphas,
    const float* __restrict__ rhos,
    const float* __restrict__ nus,
    const float* __restrict__ tau,
    const float* __restrict__ L,
    const float* __restrict__ Lam,
    float* __restrict__ out)
{
    extern __shared__ float4 smem[];               // [2][PPB][N_STEPS] = 64 KB
    float4* sfb = smem;
    float4* sdz = smem + PPB * N_STEPS;
    __shared__ float som[N_FWD];

    const int u  = threadIdx.x;                    // 0..159
    const int pl = u / N_FWD;                      // 0..3
    const int n  = u - pl * N_FWD;                 // 0..39
    const int p0 = blockIdx.x * PPB;

    const float4* fbg = &g_fbm4[(size_t)p0 * N_STEPS];
    const float4* dzg = (const float4*)dz + (size_t)p0 * N_STEPS;
    for (int i = u; i < PPB * N_STEPS; i += PT) {
        sfb[i] = fbg[i];
        float4 d = dzg[i];
        d.w = g_cw2[i & (N_STEPS - 1)];
        sdz[i] = d;
    }
    if (u < N_FWD) {
        float f0m = F0[u];
        float vsm = alphas[u] * sqrtf(fabsf(f0m + SHIFT));
        som[u] = tau[u] * vsm / (1.f + tau[u] * f0m);
    }

    float f0n = F0[n];
    float vs  = alphas[n] * sqrtf(fabsf(f0n + SHIFT));
    float rho = rhos[n];
    float nu  = nus[n];
    float sq  = sqrtf(fmaxf(1.f - rho * rho, 0.f));
    float l0 = L[n * 3 + 0], l1 = L[n * 3 + 1], l2 = L[n * 3 + 2];
    float a0 = nu * rho * l0 * LOG2E;
    float a1 = nu * rho * l1 * LOG2E;
    float a2 = nu * rho * l2 * LOG2E;
    float a3 = nu * sq * LOG2E;
    float bb = 0.5f * nu * nu * DT * LOG2E;
    float w0 = vs * l0, w1 = vs * l1, w2 = vs * l2;

    __syncthreads();

    float mdot = 0.f;
    #pragma unroll 8
    for (int m = 0; m < N_FWD; ++m)
        mdot = fmaf(Lam[n * N_FWD + m], som[m], mdot);
    float mu0dt = -vs * mdot * DT;

    const float4* fbp = sfb + pl * N_STEPS;
    const float4* dzp = sdz + pl * N_STEPS;
    float acc = f0n;
    float* op = out + (size_t)(p0 + pl) * 513 * N_FWD + n;
    __stcs(op, acc);                               // row 0 = F0
    op += N_FWD;

#define SCAN_STEP(fv, dv)                                         \
    do {                                                          \
        float arg = fmaf(a0, (fv).x,                              \
                    fmaf(a1, (fv).y,                              \
                    fmaf(a2, (fv).z,                              \
                    fmaf(a3, (fv).w, -bb * (dv).w))));            \
        float uv;                                                 \
        asm("ex2.approx.f32 %0, %1;" : "=f"(uv) : "f"(arg));      \
        float wr = fmaf(w0, (dv).x, fmaf(w1, (dv).y, w2 * (dv).z)); \
        acc = fmaf(uv, fmaf(mu0dt, uv, wr), acc);                 \
        __stcs(op, acc);                                          \
        op += N_FWD;                                              \
    } while (0)

    float4 fA[4], dA[4], fB[4], dB[4];
    #pragma unroll
    for (int i = 0; i < 4; ++i) { fA[i] = fbp[i]; dA[i] = dzp[i]; }

    #pragma unroll 1
    for (int tb = 0; tb < N_STEPS; tb += 8) {
        #pragma unroll
        for (int i = 0; i < 4; ++i) { fB[i] = fbp[tb + 4 + i]; dB[i] = dzp[tb + 4 + i]; }
        #pragma unroll
        for (int i = 0; i < 4; ++i) SCAN_STEP(fA[i], dA[i]);
        if (tb + 8 < N_STEPS) {
            #pragma unroll
            for (int i = 0; i < 4; ++i) { fA[i] = fbp[tb + 8 + i]; dA[i] = dzp[tb + 8 + i]; }
        }
        #pragma unroll
        for (int i = 0; i < 4; ++i) SCAN_STEP(fB[i], dB[i]);
    }
#undef SCAN_STEP
}

extern "C" void kernel_launch(void* const* d_in, const int* in_sizes, int n_in,
                              void* d_out, int out_size) {
    const float* dz     = (const float*)d_in[0];
    const float* F0     = (const float*)d_in[1];
    const float* alphas = (const float*)d_in[2];
    const float* rhos   = (const float*)d_in[3];
    const float* nus    = (const float*)d_in[4];
    const float* tau    = (const float*)d_in[5];
    const float* L      = (const float*)d_in[6];
    const float* Lam    = (const float*)d_in[7];
    float* out = (float*)d_out;

    const int smem_conv = (E_ROWS * SA + 2 * TILE_U + N_STEPS + 256) * 4;  // ~124.5 KB
    const int smem_path = 2 * PPB * N_STEPS * (int)sizeof(float4);         // 64 KB
    cudaFuncSetAttribute(k_conv_mma, cudaFuncAttributeMaxDynamicSharedMemorySize, smem_conv);
    cudaFuncSetAttribute(k_path, cudaFuncAttributeMaxDynamicSharedMemorySize, smem_path);

    k_conv_mma<<<256, 256, smem_conv>>>(dz);
    k_path<<<N_PATHS / PPB, PT, smem_path>>>(dz, F0, alphas, rhos, nus, tau, L, Lam, out);
}